// round 10
// baseline (speedup 1.0000x reference)
#include <cuda_runtime.h>
#include <math.h>

// Problem shape (fixed by the dataset): B=8, Q=K=2048, D=128, fp32.
#define BATCH   8
#define SEQ     2048
#define DH      128
#define BM      128          // q rows per CTA
#define BN      64           // keys per mainloop tile
#define THREADS 256
#define NEGVAL  (-1000000.0f)

// Shared memory layout (float4 units):
//   Qs: BM x 32 chunks (swizzled)      = 4096 f4  (64 KB)
//   Ks: BN x 32 chunks (swizzled)      = 2048 f4  (32 KB)
//   Vs: BN x 32 chunks (plain)         = 2048 f4  (32 KB)
//   Ps: BM x 16 chunks (plain)         = 2048 f4  (32 KB)
//   maskf: BN floats                   = 256 B
#define QS_F4   (BM * 32)
#define KS_F4   (BN * 32)
#define VS_F4   (BN * 32)
#define PS_F4   (BM * 16)
#define SMEM_BYTES ((QS_F4 + KS_F4 + VS_F4 + PS_F4) * 16 + BN * 4)

// XOR swizzle: permute 16B chunks within a 512B row so that strided row
// accesses (stride 4 rows) land in distinct bank groups.
__device__ __forceinline__ int swz(int row, int c) {
    return c ^ ((row >> 2) & 7);
}

__global__ void __launch_bounds__(THREADS, 1)
attn_fwd_kernel(const float* __restrict__ Qg,
                const float* __restrict__ Kg,
                const float* __restrict__ Vg,
                const int*   __restrict__ Mg,
                float*       __restrict__ Og)
{
    extern __shared__ float smem[];
    float4* Qs = reinterpret_cast<float4*>(smem);
    float4* Ks = Qs + QS_F4;
    float4* Vs = Ks + KS_F4;
    float4* Ps = Vs + VS_F4;
    float*  maskf = reinterpret_cast<float*>(Ps + PS_F4);

    const int tid = threadIdx.x;
    const int tm  = tid >> 4;   // 0..15 : owns q rows tm*8 .. tm*8+7
    const int tn  = tid & 15;   // 0..15 : GEMM1 key cols tn*4.., GEMM2 dv chunks (tn, tn+16)

    const int qtile = blockIdx.x;            // 0..127
    const int b     = qtile >> 4;            // 16 q-tiles per batch
    const int qrow0 = (qtile & 15) * BM;

    const float scale = 0.08838834764831845f; // 1/sqrt(128)

    // ---- Stage Q tile (prescaled by 1/sqrt(D)), swizzled ----
    {
        const float4* Qg4 = reinterpret_cast<const float4*>(Qg + (size_t)(b * SEQ + qrow0) * DH);
        #pragma unroll
        for (int t = 0; t < QS_F4 / THREADS; t++) {     // 16
            int idx = tid + t * THREADS;
            int row = idx >> 5;
            int c   = idx & 31;
            float4 v = Qg4[idx];
            v.x *= scale; v.y *= scale; v.z *= scale; v.w *= scale;
            Qs[row * 32 + swz(row, c)] = v;
        }
    }

    // Accumulators / online-softmax state (replicated across the 16 lanes of each tm group)
    float O[8][8];
    float mrow[8], lrow[8];
    #pragma unroll
    for (int i = 0; i < 8; i++) {
        mrow[i] = -1e30f;
        lrow[i] = 0.0f;
        #pragma unroll
        for (int j = 0; j < 8; j++) O[i][j] = 0.0f;
    }

    for (int kt = 0; kt < SEQ / BN; kt++) {   // 32 tiles
        __syncthreads();   // previous GEMM2 finished with K/V/P

        // ---- Stage K (swizzled), V (plain), mask ----
        const float4* Kg4 = reinterpret_cast<const float4*>(Kg + (size_t)(b * SEQ + kt * BN) * DH);
        const float4* Vg4 = reinterpret_cast<const float4*>(Vg + (size_t)(b * SEQ + kt * BN) * DH);
        #pragma unroll
        for (int t = 0; t < KS_F4 / THREADS; t++) {     // 8
            int idx = tid + t * THREADS;
            int row = idx >> 5;
            int c   = idx & 31;
            Ks[row * 32 + swz(row, c)] = Kg4[idx];
            Vs[idx] = Vg4[idx];
        }
        if (tid < BN) maskf[tid] = (float)Mg[(size_t)b * SEQ + kt * BN + tid];
        __syncthreads();

        // ---- GEMM1: S[8][4] = Q(rows tm*8..) . K^T(cols tn*4..) ----
        float S[8][4];
        #pragma unroll
        for (int i = 0; i < 8; i++)
            #pragma unroll
            for (int j = 0; j < 4; j++) S[i][j] = 0.0f;

        #pragma unroll 4
        for (int d4 = 0; d4 < 32; d4++) {
            float4 kf[4];
            #pragma unroll
            for (int j = 0; j < 4; j++) {
                int kr = tn * 4 + j;
                kf[j] = Ks[kr * 32 + swz(kr, d4)];
            }
            #pragma unroll
            for (int i = 0; i < 8; i++) {
                int qr = tm * 8 + i;
                float4 q = Qs[qr * 32 + swz(qr, d4)];
                #pragma unroll
                for (int j = 0; j < 4; j++) {
                    S[i][j] += q.x * kf[j].x;
                    S[i][j] += q.y * kf[j].y;
                    S[i][j] += q.z * kf[j].z;
                    S[i][j] += q.w * kf[j].w;
                }
            }
        }

        // ---- Mask (exact reference semantics: masked -> -1e6 before softmax) ----
        float mk0 = maskf[tn * 4 + 0];
        float mk1 = maskf[tn * 4 + 1];
        float mk2 = maskf[tn * 4 + 2];
        float mk3 = maskf[tn * 4 + 3];
        #pragma unroll
        for (int i = 0; i < 8; i++) {
            S[i][0] = (mk0 != 0.0f) ? S[i][0] : NEGVAL;
            S[i][1] = (mk1 != 0.0f) ? S[i][1] : NEGVAL;
            S[i][2] = (mk2 != 0.0f) ? S[i][2] : NEGVAL;
            S[i][3] = (mk3 != 0.0f) ? S[i][3] : NEGVAL;
        }

        // ---- Online softmax per q row; write P tile to smem ----
        #pragma unroll
        for (int i = 0; i < 8; i++) {
            float rmax = fmaxf(fmaxf(S[i][0], S[i][1]), fmaxf(S[i][2], S[i][3]));
            #pragma unroll
            for (int off = 8; off >= 1; off >>= 1)
                rmax = fmaxf(rmax, __shfl_xor_sync(0xffffffffu, rmax, off));
            float mnew = fmaxf(mrow[i], rmax);
            float corr = __expf(mrow[i] - mnew);
            mrow[i] = mnew;
            float rsum = 0.0f;
            #pragma unroll
            for (int j = 0; j < 4; j++) {
                S[i][j] = __expf(S[i][j] - mnew);
                rsum += S[i][j];
            }
            #pragma unroll
            for (int off = 8; off >= 1; off >>= 1)
                rsum += __shfl_xor_sync(0xffffffffu, rsum, off);
            lrow[i] = lrow[i] * corr + rsum;
            #pragma unroll
            for (int j = 0; j < 8; j++) O[i][j] *= corr;
            Ps[(tm * 8 + i) * 16 + tn] = make_float4(S[i][0], S[i][1], S[i][2], S[i][3]);
        }
        __syncthreads();

        // ---- GEMM2: O[8][8] += P(rows tm*8..) . V ; dv chunks (tn, tn+16) ----
        #pragma unroll 4
        for (int n4 = 0; n4 < BN / 4; n4++) {    // 16
            float4 vf0[4], vf1[4];
            #pragma unroll
            for (int jj = 0; jj < 4; jj++) {
                int vr = n4 * 4 + jj;
                vf0[jj] = Vs[vr * 32 + tn];
                vf1[jj] = Vs[vr * 32 + 16 + tn];
            }
            #pragma unroll
            for (int i = 0; i < 8; i++) {
                float4 p = Ps[(tm * 8 + i) * 16 + n4];
                float pj[4] = {p.x, p.y, p.z, p.w};
                #pragma unroll
                for (int jj = 0; jj < 4; jj++) {
                    O[i][0] += pj[jj] * vf0[jj].x;
                    O[i][1] += pj[jj] * vf0[jj].y;
                    O[i][2] += pj[jj] * vf0[jj].z;
                    O[i][3] += pj[jj] * vf0[jj].w;
                    O[i][4] += pj[jj] * vf1[jj].x;
                    O[i][5] += pj[jj] * vf1[jj].y;
                    O[i][6] += pj[jj] * vf1[jj].z;
                    O[i][7] += pj[jj] * vf1[jj].w;
                }
            }
        }
    }

    // ---- Epilogue: normalize and store (dv chunks tn and tn+16) ----
    #pragma unroll
    for (int i = 0; i < 8; i++) {
        float inv = 1.0f / lrow[i];
        int qr = qrow0 + tm * 8 + i;
        float4* out4 = reinterpret_cast<float4*>(Og + (size_t)(b * SEQ + qr) * DH);
        out4[tn]      = make_float4(O[i][0] * inv, O[i][1] * inv, O[i][2] * inv, O[i][3] * inv);
        out4[16 + tn] = make_float4(O[i][4] * inv, O[i][5] * inv, O[i][6] * inv, O[i][7] * inv);
    }
}

extern "C" void kernel_launch(void* const* d_in, const int* in_sizes, int n_in,
                              void* d_out, int out_size) {
    const float* Qg = (const float*)d_in[0];
    const float* Kg = (const float*)d_in[1];
    const float* Vg = (const float*)d_in[2];
    const int*   Mg = (const int*)d_in[3];
    float* Og = (float*)d_out;

    // Idempotent; legal during graph capture (not a stream op, not an allocation).
    cudaFuncSetAttribute(attn_fwd_kernel,
                         cudaFuncAttributeMaxDynamicSharedMemorySize, SMEM_BYTES);

    dim3 grid(BATCH * SEQ / BM);   // 128 CTAs, single wave on 148 SMs
    attn_fwd_kernel<<<grid, THREADS, SMEM_BYTES>>>(Qg, Kg, Vg, Mg, Og);
}

// round 11
// speedup vs baseline: 1.0048x; 1.0048x over previous
#include <cuda_runtime.h>
#include <math.h>

// Problem shape (fixed by the dataset): B=8, Q=K=2048, D=128, fp32.
#define BATCH   8
#define SEQ     2048
#define DH      128
#define BM      128          // q rows per CTA
#define BN      64           // keys per mainloop tile
#define THREADS 256
#define NEGVAL  (-1000000.0f)

// Shared memory layout (float4 units):
//   Qs: BM x 32 chunks (swizzled)      = 4096 f4  (64 KB)
//   Ks: BN x 32 chunks (swizzled)      = 2048 f4  (32 KB)
//   Vs: BN x 32 chunks (plain)         = 2048 f4  (32 KB)
//   Ps: BM x 16 chunks (plain)         = 2048 f4  (32 KB)
//   maskf: BN floats                   = 256 B
#define QS_F4   (BM * 32)
#define KS_F4   (BN * 32)
#define VS_F4   (BN * 32)
#define PS_F4   (BM * 16)
#define SMEM_BYTES ((QS_F4 + KS_F4 + VS_F4 + PS_F4) * 16 + BN * 4)

// XOR swizzle: permute 16B chunks within a 512B row so that strided row
// accesses (stride 4 rows) land in distinct bank groups.
__device__ __forceinline__ int swz(int row, int c) {
    return c ^ ((row >> 2) & 7);
}

__global__ void __launch_bounds__(THREADS, 1)
attn_fwd_kernel(const float* __restrict__ Qg,
                const float* __restrict__ Kg,
                const float* __restrict__ Vg,
                const int*   __restrict__ Mg,
                float*       __restrict__ Og)
{
    extern __shared__ float smem[];
    float4* Qs = reinterpret_cast<float4*>(smem);
    float4* Ks = Qs + QS_F4;
    float4* Vs = Ks + KS_F4;
    float4* Ps = Vs + VS_F4;
    float*  maskf = reinterpret_cast<float*>(Ps + PS_F4);

    const int tid = threadIdx.x;
    const int tm  = tid >> 4;   // 0..15 : owns q rows tm*8 .. tm*8+7
    const int tn  = tid & 15;   // 0..15 : GEMM1 key cols tn*4.., GEMM2 dv chunks (tn, tn+16)

    const int qtile = blockIdx.x;            // 0..127
    const int b     = qtile >> 4;            // 16 q-tiles per batch
    const int qrow0 = (qtile & 15) * BM;

    const float scale = 0.08838834764831845f; // 1/sqrt(128)

    // ---- Stage Q tile (prescaled by 1/sqrt(D)), swizzled ----
    {
        const float4* Qg4 = reinterpret_cast<const float4*>(Qg + (size_t)(b * SEQ + qrow0) * DH);
        #pragma unroll
        for (int t = 0; t < QS_F4 / THREADS; t++) {     // 16
            int idx = tid + t * THREADS;
            int row = idx >> 5;
            int c   = idx & 31;
            float4 v = Qg4[idx];
            v.x *= scale; v.y *= scale; v.z *= scale; v.w *= scale;
            Qs[row * 32 + swz(row, c)] = v;
        }
    }

    // Accumulators / online-softmax state (replicated across the 16 lanes of each tm group)
    float O[8][8];
    float mrow[8], lrow[8];
    #pragma unroll
    for (int i = 0; i < 8; i++) {
        mrow[i] = -1e30f;
        lrow[i] = 0.0f;
        #pragma unroll
        for (int j = 0; j < 8; j++) O[i][j] = 0.0f;
    }

    for (int kt = 0; kt < SEQ / BN; kt++) {   // 32 tiles
        __syncthreads();   // previous GEMM2 finished with K/V/P

        // ---- Stage K (swizzled), V (plain), mask ----
        const float4* Kg4 = reinterpret_cast<const float4*>(Kg + (size_t)(b * SEQ + kt * BN) * DH);
        const float4* Vg4 = reinterpret_cast<const float4*>(Vg + (size_t)(b * SEQ + kt * BN) * DH);
        #pragma unroll
        for (int t = 0; t < KS_F4 / THREADS; t++) {     // 8
            int idx = tid + t * THREADS;
            int row = idx >> 5;
            int c   = idx & 31;
            Ks[row * 32 + swz(row, c)] = Kg4[idx];
            Vs[idx] = Vg4[idx];
        }
        if (tid < BN) maskf[tid] = (float)Mg[(size_t)b * SEQ + kt * BN + tid];
        __syncthreads();

        // ---- GEMM1: S[8][4] = Q(rows tm*8..) . K^T(cols tn*4..) ----
        float S[8][4];
        #pragma unroll
        for (int i = 0; i < 8; i++)
            #pragma unroll
            for (int j = 0; j < 4; j++) S[i][j] = 0.0f;

        #pragma unroll 4
        for (int d4 = 0; d4 < 32; d4++) {
            float4 kf[4];
            #pragma unroll
            for (int j = 0; j < 4; j++) {
                int kr = tn * 4 + j;
                kf[j] = Ks[kr * 32 + swz(kr, d4)];
            }
            #pragma unroll
            for (int i = 0; i < 8; i++) {
                int qr = tm * 8 + i;
                float4 q = Qs[qr * 32 + swz(qr, d4)];
                #pragma unroll
                for (int j = 0; j < 4; j++) {
                    S[i][j] += q.x * kf[j].x;
                    S[i][j] += q.y * kf[j].y;
                    S[i][j] += q.z * kf[j].z;
                    S[i][j] += q.w * kf[j].w;
                }
            }
        }

        // ---- Mask (exact reference semantics: masked -> -1e6 before softmax) ----
        float mk0 = maskf[tn * 4 + 0];
        float mk1 = maskf[tn * 4 + 1];
        float mk2 = maskf[tn * 4 + 2];
        float mk3 = maskf[tn * 4 + 3];
        #pragma unroll
        for (int i = 0; i < 8; i++) {
            S[i][0] = (mk0 != 0.0f) ? S[i][0] : NEGVAL;
            S[i][1] = (mk1 != 0.0f) ? S[i][1] : NEGVAL;
            S[i][2] = (mk2 != 0.0f) ? S[i][2] : NEGVAL;
            S[i][3] = (mk3 != 0.0f) ? S[i][3] : NEGVAL;
        }

        // ---- Online softmax per q row; write P tile to smem ----
        #pragma unroll
        for (int i = 0; i < 8; i++) {
            float rmax = fmaxf(fmaxf(S[i][0], S[i][1]), fmaxf(S[i][2], S[i][3]));
            #pragma unroll
            for (int off = 8; off >= 1; off >>= 1)
                rmax = fmaxf(rmax, __shfl_xor_sync(0xffffffffu, rmax, off));
            float mnew = fmaxf(mrow[i], rmax);
            float corr = __expf(mrow[i] - mnew);
            mrow[i] = mnew;
            float rsum = 0.0f;
            #pragma unroll
            for (int j = 0; j < 4; j++) {
                S[i][j] = __expf(S[i][j] - mnew);
                rsum += S[i][j];
            }
            #pragma unroll
            for (int off = 8; off >= 1; off >>= 1)
                rsum += __shfl_xor_sync(0xffffffffu, rsum, off);
            lrow[i] = lrow[i] * corr + rsum;
            #pragma unroll
            for (int j = 0; j < 8; j++) O[i][j] *= corr;
            Ps[(tm * 8 + i) * 16 + tn] = make_float4(S[i][0], S[i][1], S[i][2], S[i][3]);
        }
        __syncthreads();

        // ---- GEMM2: O[8][8] += P(rows tm*8..) . V ; dv chunks (tn, tn+16) ----
        #pragma unroll 4
        for (int n4 = 0; n4 < BN / 4; n4++) {    // 16
            float4 vf0[4], vf1[4];
            #pragma unroll
            for (int jj = 0; jj < 4; jj++) {
                int vr = n4 * 4 + jj;
                vf0[jj] = Vs[vr * 32 + tn];
                vf1[jj] = Vs[vr * 32 + 16 + tn];
            }
            #pragma unroll
            for (int i = 0; i < 8; i++) {
                float4 p = Ps[(tm * 8 + i) * 16 + n4];
                float pj[4] = {p.x, p.y, p.z, p.w};
                #pragma unroll
                for (int jj = 0; jj < 4; jj++) {
                    O[i][0] += pj[jj] * vf0[jj].x;
                    O[i][1] += pj[jj] * vf0[jj].y;
                    O[i][2] += pj[jj] * vf0[jj].z;
                    O[i][3] += pj[jj] * vf0[jj].w;
                    O[i][4] += pj[jj] * vf1[jj].x;
                    O[i][5] += pj[jj] * vf1[jj].y;
                    O[i][6] += pj[jj] * vf1[jj].z;
                    O[i][7] += pj[jj] * vf1[jj].w;
                }
            }
        }
    }

    // ---- Epilogue: normalize and store (dv chunks tn and tn+16) ----
    #pragma unroll
    for (int i = 0; i < 8; i++) {
        float inv = 1.0f / lrow[i];
        int qr = qrow0 + tm * 8 + i;
        float4* out4 = reinterpret_cast<float4*>(Og + (size_t)(b * SEQ + qr) * DH);
        out4[tn]      = make_float4(O[i][0] * inv, O[i][1] * inv, O[i][2] * inv, O[i][3] * inv);
        out4[16 + tn] = make_float4(O[i][4] * inv, O[i][5] * inv, O[i][6] * inv, O[i][7] * inv);
    }
}

extern "C" void kernel_launch(void* const* d_in, const int* in_sizes, int n_in,
                              void* d_out, int out_size) {
    const float* Qg = (const float*)d_in[0];
    const float* Kg = (const float*)d_in[1];
    const float* Vg = (const float*)d_in[2];
    const int*   Mg = (const int*)d_in[3];
    float* Og = (float*)d_out;

    // Idempotent; legal during graph capture (not a stream op, not an allocation).
    cudaFuncSetAttribute(attn_fwd_kernel,
                         cudaFuncAttributeMaxDynamicSharedMemorySize, SMEM_BYTES);

    dim3 grid(BATCH * SEQ / BM);   // 128 CTAs, single wave on 148 SMs
    attn_fwd_kernel<<<grid, THREADS, SMEM_BYTES>>>(Qg, Kg, Vg, Mg, Og);
}